// round 13
// baseline (speedup 1.0000x reference)
#include <cuda_runtime.h>
#include <cstdint>

#define NSEQ 2048
#define DD 512
#define VV 512
#define CL 16

static __device__ float g_X [NSEQ * DD];
static __device__ float g_XW[NSEQ * DD];
static __device__ float g_H2[NSEQ * DD];
static __device__ float g_O [NSEQ * VV];
static __device__ float g_E [VV * VV];
static __device__ int   g_hflag[NSEQ];
static __device__ int   g_oflag[NSEQ];
static __device__ int   g_is64;

__device__ __forceinline__ uint32_t ctarank() {
    uint32_t r; asm("mov.u32 %0, %%cluster_ctarank;" : "=r"(r)); return r;
}
__device__ __forceinline__ uint32_t s2u(const void* p) {
    uint32_t a;
    asm("{ .reg .u64 t; cvta.to.shared.u64 t, %1; cvt.u32.u64 %0, t; }" : "=r"(a) : "l"(p));
    return a;
}
__device__ __forceinline__ uint32_t mapa_(uint32_t laddr, uint32_t r) {
    uint32_t a; asm("mapa.shared::cluster.u32 %0, %1, %2;" : "=r"(a) : "r"(laddr), "r"(r));
    return a;
}
__device__ __forceinline__ float4 ld128r(uint32_t raddr) {
    float4 v;
    asm volatile("ld.shared::cluster.v4.f32 {%0, %1, %2, %3}, [%4];"
                 : "=f"(v.x), "=f"(v.y), "=f"(v.z), "=f"(v.w) : "r"(raddr) : "memory");
    return v;
}
__device__ __forceinline__ void arrive_rel(uint32_t rmbar) {
    asm volatile("mbarrier.arrive.release.cluster.shared::cluster.b64 _, [%0];"
                 :: "r"(rmbar) : "memory");
}
__device__ __forceinline__ void mbar_init(uint32_t mb, uint32_t cnt) {
    asm volatile("mbarrier.init.shared.b64 [%0], %1;" :: "r"(mb), "r"(cnt) : "memory");
}
__device__ __forceinline__ void mbar_wait(uint32_t mb, uint32_t parity) {
    asm volatile(
        "{\n\t.reg .pred P;\n"
        "W%=:\n\t"
        "mbarrier.try_wait.parity.acquire.cluster.shared::cta.b64 P, [%0], %1, 0x989680;\n\t"
        "@!P bra W%=;\n\t}"
        :: "r"(mb), "r"(parity) : "memory");
}
__device__ __forceinline__ void cl_sync() {
    asm volatile("barrier.cluster.arrive.aligned;" ::: "memory");
    asm volatile("barrier.cluster.wait.aligned;"   ::: "memory");
}
__device__ __forceinline__ int ld_acq(const int* p) {
    int v; asm volatile("ld.acquire.gpu.global.b32 %0, [%1];" : "=r"(v) : "l"(p) : "memory");
    return v;
}
__device__ __forceinline__ void st_rel(int* p, int v) {
    asm volatile("st.release.gpu.global.b32 [%0], %1;" :: "l"(p), "r"(v) : "memory");
}
__device__ __forceinline__ void wait_flag(const int* p) {
    while (ld_acq(p) == 0) { asm volatile("nanosleep.u32 128;"); }
}
__device__ __forceinline__ float wsum(float x) {
#pragma unroll
    for (int o = 16; o; o >>= 1) x += __shfl_xor_sync(0xffffffffu, x, o);
    return x;
}
__device__ __forceinline__ float ex2f_(float x) {
    float y; asm("ex2.approx.f32 %0, %1;" : "=f"(y) : "f"(x)); return y;
}
__device__ __forceinline__ float lg2f_(float x) {
    float y; asm("lg2.approx.f32 %0, %1;" : "=f"(y) : "f"(x)); return y;
}
__device__ __forceinline__ float rcpf_(float x) {
    float y; asm("rcp.approx.f32 %0, %1;" : "=f"(y) : "f"(x)); return y;
}
__device__ __forceinline__ float tanh_ex2(float x) {
    float t = ex2f_(2.8853900817779268f * x);
    float r = rcpf_(t + 1.0f);
    return fmaf(-2.0f, r, 1.0f);
}
__device__ __forceinline__ uint64_t pack2(float a, float b) {
    uint64_t d; asm("mov.b64 %0, {%1, %2};" : "=l"(d) : "f"(a), "f"(b)); return d;
}
__device__ __forceinline__ uint64_t fma2(uint64_t a, uint64_t b, uint64_t c) {
    uint64_t d; asm("fma.rn.f32x2 %0, %1, %2, %3;" : "=l"(d) : "l"(a), "l"(b), "l"(c));
    return d;
}
__device__ __forceinline__ float sum2(uint64_t v) {
    float lo, hi; asm("mov.b64 {%0, %1}, %2;" : "=f"(lo), "=f"(hi) : "l"(v));
    return lo + hi;
}

__global__ void detect_kernel(const int* __restrict__ w) {
    __shared__ int any;
    if (threadIdx.x == 0) any = 0;
    __syncthreads();
    int acc = 0;
    for (int i = threadIdx.x; i < NSEQ / 2; i += blockDim.x) acc |= w[2 * i + 1];
    if (acc) atomicOr(&any, 1);
    __syncthreads();
    if (threadIdx.x == 0) g_is64 = (any == 0) ? 1 : 0;
}
__global__ void gather_kernel(const void* __restrict__ nums, const float* __restrict__ emb) {
    int t = blockIdx.x;
    long long idx = g_is64 ? ((const long long*)nums)[t]
                           : (long long)((const int*)nums)[t];
    const float4* src = (const float4*)(emb + (size_t)idx * DD);
    float4* dst = (float4*)(&g_X[(size_t)t * DD]);
    dst[threadIdx.x] = src[threadIdx.x];
}
__global__ void expT_kernel(const float* __restrict__ T) {
    int i = blockIdx.x * 256 + threadIdx.x;
    g_E[i] = ex2f_(T[i] * 1.4426950408889634f);
}
__global__ void zero_flags_kernel() {
    int i = blockIdx.x * 256 + threadIdx.x;
    g_hflag[i] = 0; g_oflag[i] = 0;
}

__global__ __launch_bounds__(256)
void gemm_bias(const float* __restrict__ A, const float* __restrict__ B,
               const float* __restrict__ bias, float* __restrict__ C)
{
    __shared__ __align__(16) float As[16][68];
    __shared__ __align__(16) float Bs[16][68];
    const int tid = threadIdx.x;
    const int bm = blockIdx.y * 64, bn = blockIdx.x * 64;
    const int tm = tid >> 4, tn = tid & 15;
    float acc[4][4] = {};
    for (int k0 = 0; k0 < 512; k0 += 16) {
        {
            int row = tid >> 2, cg = (tid & 3) * 4;
            float4 v = *(const float4*)(A + (size_t)(bm + row) * 512 + k0 + cg);
            As[cg + 0][row] = v.x; As[cg + 1][row] = v.y;
            As[cg + 2][row] = v.z; As[cg + 3][row] = v.w;
        }
        {
            int row = tid >> 4, col = (tid & 15) * 4;
            *(float4*)&Bs[row][col] = *(const float4*)(B + (size_t)(k0 + row) * 512 + bn + col);
        }
        __syncthreads();
#pragma unroll
        for (int k = 0; k < 16; k++) {
            float4 a = *(const float4*)&As[k][tm * 4];
            float4 b = *(const float4*)&Bs[k][tn * 4];
            float av[4] = {a.x, a.y, a.z, a.w};
            float bv[4] = {b.x, b.y, b.z, b.w};
#pragma unroll
            for (int i = 0; i < 4; i++)
#pragma unroll
                for (int jj = 0; jj < 4; jj++)
                    acc[i][jj] = fmaf(av[i], bv[jj], acc[i][jj]);
        }
        __syncthreads();
    }
    float4 bb = *(const float4*)(bias + bn + tn * 4);
#pragma unroll
    for (int i = 0; i < 4; i++) {
        float4 o;
        o.x = acc[i][0] + bb.x; o.y = acc[i][1] + bb.y;
        o.z = acc[i][2] + bb.z; o.w = acc[i][3] + bb.w;
        *(float4*)(C + (size_t)(bm + tm * 4 + i) * 512 + bn + tn * 4) = o;
    }
}

// ===== mega: 48 CTAs = cluster0 RNN (pull) + cluster1 alpha (pull) + 16 builders =====
__global__ void __launch_bounds__(512, 1)
mega(const float* __restrict__ Whh1, const float* __restrict__ XW1,
     const float* __restrict__ Whh2, const float* __restrict__ Wxh2,
     const float* __restrict__ b2,   const float* __restrict__ Wl,
     const float* __restrict__ bl,   float* __restrict__ out)
{
    __shared__ __align__(16) float stage[2 * 1024];   // pulled full vectors
    __shared__ __align__(16) float vals[2 * 64];      // own slice (h1|h2 or alpha)
    __shared__ __align__(8) long long mbar[2];
    __shared__ float sh_off[2];
    const int bid  = blockIdx.x;
    const int tid  = threadIdx.x;
    const int lane = tid & 31;
    const int w    = tid >> 5;
    const int seg  = lane >> 3;
    const int wo   = (lane & 7) * 4;
    const float L2E = 1.4426950408889634f;
    const float LN2 = 0.6931471805599453f;

    if (bid < 16) {
        // -------- role A: fused 2-layer RNN, pull model --------
        const uint32_t rank = ctarank();
        const int j0 = (int)rank * 32 + 2 * w;
        uint64_t w1a[8], w1b[8], xa[8], xb[8], ha[8], hb[8];
#pragma unroll
        for (int i = 0; i < 4; i++)
#pragma unroll
            for (int j = 0; j < 2; j++) {
                int k = 128 * i + 4 * lane + 2 * j;
                w1a[2*i+j] = pack2(Whh1[(size_t)k*DD + j0],   Whh1[(size_t)(k+1)*DD + j0]);
                w1b[2*i+j] = pack2(Whh1[(size_t)k*DD + j0+1], Whh1[(size_t)(k+1)*DD + j0+1]);
                xa [2*i+j] = pack2(Wxh2[(size_t)k*DD + j0],   Wxh2[(size_t)(k+1)*DD + j0]);
                xb [2*i+j] = pack2(Wxh2[(size_t)k*DD + j0+1], Wxh2[(size_t)(k+1)*DD + j0+1]);
                ha [2*i+j] = pack2(Whh2[(size_t)k*DD + j0],   Whh2[(size_t)(k+1)*DD + j0]);
                hb [2*i+j] = pack2(Whh2[(size_t)k*DD + j0+1], Whh2[(size_t)(k+1)*DD + j0+1]);
            }
        const float bj0 = b2[j0], bj1 = b2[j0 + 1];
        for (int i = tid; i < 1024; i += 512) stage[i] = 0.0f;   // stage[0]: h1=-h2=0
        const uint32_t vb = s2u(vals), mb = s2u(mbar);
        if (tid == 0) { mbar_init(mb, CL); mbar_init(mb + 8, CL); }
        __syncthreads();
        cl_sync();
        uint32_t pullA = 0, rMB = 0;
        if (lane < CL) pullA = mapa_(vb, (uint32_t)w) + (uint32_t)(lane * 16);
        if (w == 0 && lane < CL) rMB = mapa_(mb, (uint32_t)lane);
        float2 xw = *(const float2*)&XW1[j0];

#pragma unroll 1
        for (int r = 0; r <= NSEQ + 1; r++) {
            const uint32_t p = (uint32_t)(r & 1), np = (uint32_t)((r + 1) & 1);
            if (r) {
                mbar_wait(mb + 8 * p, (uint32_t)(((r - 1) >> 1) & 1));
                if (lane < CL) {
                    float4 v = ld128r(pullA + p * 256u);
                    *(float4*)&stage[p * 1024 + w * 64 + lane * 4] = v;
                }
                __syncthreads();
            }
            const float* sg = stage + p * 1024;
            if (r <= NSEQ) {
                const float* s0 = sg + seg * 64 + wo;
                ulonglong2 A = *(const ulonglong2*)(s0);
                ulonglong2 B = *(const ulonglong2*)(s0 + 256);
                ulonglong2 C = *(const ulonglong2*)(s0 + 512);
                ulonglong2 D = *(const ulonglong2*)(s0 + 768);
                if (r < NSEQ) {
                    uint64_t p0=0,p1=0,q0=0,q1=0;
                    p0=fma2(A.x,w1a[0],p0); p1=fma2(A.y,w1a[1],p1);
                    q0=fma2(A.x,w1b[0],q0); q1=fma2(A.y,w1b[1],q1);
                    p0=fma2(B.x,w1a[2],p0); p1=fma2(B.y,w1a[3],p1);
                    q0=fma2(B.x,w1b[2],q0); q1=fma2(B.y,w1b[3],q1);
                    p0=fma2(C.x,w1a[4],p0); p1=fma2(C.y,w1a[5],p1);
                    q0=fma2(C.x,w1b[4],q0); q1=fma2(C.y,w1b[5],q1);
                    p0=fma2(D.x,w1a[6],p0); p1=fma2(D.y,w1a[7],p1);
                    q0=fma2(D.x,w1b[6],q0); q1=fma2(D.y,w1b[7],q1);
                    float ps = wsum(sum2(p0) + sum2(p1));
                    float qs = wsum(sum2(q0) + sum2(q1));
                    if (lane == 0)
                        *(float2*)&vals[np * 64 + 2 * w] =
                            make_float2(tanh_ex2(xw.x + ps), tanh_ex2(xw.y + qs));
                }
                uint64_t u0_=0,u1_=0,v0_=0,v1_=0;
                u0_=fma2(A.x,xa[0],u0_); u1_=fma2(A.y,xa[1],u1_);
                v0_=fma2(A.x,xb[0],v0_); v1_=fma2(A.y,xb[1],v1_);
                u0_=fma2(B.x,xa[2],u0_); u1_=fma2(B.y,xa[3],u1_);
                v0_=fma2(B.x,xb[2],v0_); v1_=fma2(B.y,xb[3],v1_);
                u0_=fma2(C.x,xa[4],u0_); u1_=fma2(C.y,xa[5],u1_);
                v0_=fma2(C.x,xb[4],v0_); v1_=fma2(C.y,xb[5],v1_);
                u0_=fma2(D.x,xa[6],u0_); u1_=fma2(D.y,xa[7],u1_);
                v0_=fma2(D.x,xb[6],v0_); v1_=fma2(D.y,xb[7],v1_);
                ulonglong2 E = *(const ulonglong2*)(s0 + 32);
                ulonglong2 F = *(const ulonglong2*)(s0 + 288);
                ulonglong2 G = *(const ulonglong2*)(s0 + 544);
                ulonglong2 H = *(const ulonglong2*)(s0 + 800);
                u0_=fma2(E.x,ha[0],u0_); u1_=fma2(E.y,ha[1],u1_);
                v0_=fma2(E.x,hb[0],v0_); v1_=fma2(E.y,hb[1],v1_);
                u0_=fma2(F.x,ha[2],u0_); u1_=fma2(F.y,ha[3],u1_);
                v0_=fma2(F.x,hb[2],v0_); v1_=fma2(F.y,hb[3],v1_);
                u0_=fma2(G.x,ha[4],u0_); u1_=fma2(G.y,ha[5],u1_);
                v0_=fma2(G.x,hb[4],v0_); v1_=fma2(G.y,hb[5],v1_);
                u0_=fma2(H.x,ha[6],u0_); u1_=fma2(H.y,ha[7],u1_);
                v0_=fma2(H.x,hb[6],v0_); v1_=fma2(H.y,hb[7],v1_);
                float us = wsum(sum2(u0_) + sum2(u1_));
                float vs = wsum(sum2(v0_) + sum2(v1_));
                float h0 = (r >= 1) ? tanh_ex2(us + bj0) : 0.0f;
                float h1 = (r >= 1) ? tanh_ex2(vs + bj1) : 0.0f;
                if (lane == 0) *(float2*)&vals[np * 64 + 32 + 2 * w] = make_float2(h0, h1);
                __syncthreads();
                if (w == 0 && lane < CL) arrive_rel(rMB + 8u * np);
            }
            if (r >= 2 && (int)rank == ((r - 2) & 15)) {   // publish row r-2 from stage
                int row = r - 2;
                g_H2[(size_t)row * DD + tid] = sg[(tid >> 5) * 64 + 32 + (tid & 31)];
                __syncthreads();
                if (tid == 0) st_rel(&g_hflag[row], 1);
            }
            if (r + 1 < NSEQ) xw = *(const float2*)&XW1[(size_t)(r + 1) * DD + j0];
        }
        cl_sync();
    } else if (bid < 32) {
        // -------- role B: forward CRF alpha, pull model, exp folded into pull --------
        const uint32_t rank = ctarank();
        const int u0 = (int)rank * 32 + 2 * w;
        uint64_t e0p[8], e1p[8];
#pragma unroll
        for (int i = 0; i < 4; i++)
#pragma unroll
            for (int j = 0; j < 2; j++) {
                int k = 128 * i + 4 * lane + 2 * j;
                e0p[2*i+j] = pack2(g_E[(size_t)k*VV + u0],     g_E[(size_t)(k+1)*VV + u0]);
                e1p[2*i+j] = pack2(g_E[(size_t)k*VV + u0 + 1], g_E[(size_t)(k+1)*VV + u0 + 1]);
            }
        for (int i = tid; i < 512; i += 512) stage[i] = 0.0f;
        if (tid == 0) stage[0] = 1.0f;                 // exp(alpha0 - offc): 1 at BOS
        const uint32_t vb = s2u(vals), mb = s2u(mbar);
        if (tid == 0) { mbar_init(mb, CL); mbar_init(mb + 8, CL); }
        __syncthreads();
        cl_sync();
        uint32_t pullB = 0, rMB = 0;
        if (lane < 8) pullB = mapa_(vb, (uint32_t)w) + (uint32_t)(lane * 16);
        if (w == 0 && lane < CL) rMB = mapa_(mb, (uint32_t)lane);
        wait_flag(&g_oflag[0]);
        float offc = g_O[0] * L2E;                     // alpha_0[BOS]
        wait_flag(&g_oflag[1]);
        float2 ov = *(const float2*)&g_O[(size_t)VV + u0];
        float o0 = ov.x * L2E, o1 = ov.y * L2E;

#pragma unroll 1
        for (int si = 0; si < NSEQ - 1; si++) {
            const uint32_t p = (uint32_t)(si & 1), np = (uint32_t)((si + 1) & 1);
            if (si) {
                mbar_wait(mb + 8 * p, (uint32_t)(((si - 1) >> 1) & 1));
                if (lane < 8) {
                    float4 v = ld128r(pullB + p * 128u);
                    float4 e;
                    e.x = ex2f_(v.x - offc); e.y = ex2f_(v.y - offc);
                    e.z = ex2f_(v.z - offc); e.w = ex2f_(v.w - offc);
                    *(float4*)&stage[p * 512 + w * 32 + lane * 4] = e;
                    if (w == 0 && lane == 0) sh_off[p] = v.x;    // raw alpha[0]
                }
                __syncthreads();
            }
            const float* s0 = stage + p * 512 + seg * 32 + wo;
            ulonglong2 A = *(const ulonglong2*)(s0);
            ulonglong2 B = *(const ulonglong2*)(s0 + 128);
            ulonglong2 C = *(const ulonglong2*)(s0 + 256);
            ulonglong2 D = *(const ulonglong2*)(s0 + 384);
            uint64_t p0=0,p1=0,q0=0,q1=0;
            p0=fma2(A.x,e0p[0],p0); p1=fma2(A.y,e0p[1],p1);
            q0=fma2(A.x,e1p[0],q0); q1=fma2(A.y,e1p[1],q1);
            p0=fma2(B.x,e0p[2],p0); p1=fma2(B.y,e0p[3],p1);
            q0=fma2(B.x,e1p[2],q0); q1=fma2(B.y,e1p[3],q1);
            p0=fma2(C.x,e0p[4],p0); p1=fma2(C.y,e0p[5],p1);
            q0=fma2(C.x,e1p[4],q0); q1=fma2(C.y,e1p[5],q1);
            p0=fma2(D.x,e0p[6],p0); p1=fma2(D.y,e0p[7],p1);
            q0=fma2(D.x,e1p[6],q0); q1=fma2(D.y,e1p[7],q1);
            float s0v = wsum(sum2(p0) + sum2(p1));
            float s1v = wsum(sum2(q0) + sum2(q1));
            float al0 = o0 + offc + lg2f_(s0v);
            float al1 = o1 + offc + lg2f_(s1v);
            if (si) offc = sh_off[p];                   // next round's exp offset
            if (si == NSEQ - 2) {
                if (rank == 0 && tid == 0) out[0] = al1 * LN2;   // alpha_{n-1}[EOS]
            } else {
                if (lane == 0) *(float2*)&vals[np * 32 + 2 * w] = make_float2(al0, al1);
                __syncthreads();
                if (w == 0 && lane < CL) arrive_rel(rMB + 8u * np);
                int row = si + 2;
                wait_flag(&g_oflag[row]);
                float2 onx = *(const float2*)&g_O[(size_t)row * VV + u0];
                o0 = onx.x * L2E; o1 = onx.y * L2E;
            }
        }
        cl_sync();
    } else {
        // -------- role C: O-row builders --------
        const int b = bid - 32;
        for (int row = b; row < NSEQ; row += 16) {
            wait_flag(&g_hflag[row]);
            stage[tid] = g_H2[(size_t)row * DD + tid];
            __syncthreads();
            float acc = bl[tid];
            const float* wc = Wl + tid;
#pragma unroll 16
            for (int k = 0; k < DD; k++) acc = fmaf(stage[k], wc[(size_t)k * VV], acc);
            g_O[(size_t)row * VV + tid] = acc;
            __syncthreads();
            if (tid == 0) st_rel(&g_oflag[row], 1);
        }
    }
}

extern "C" void kernel_launch(void* const* d_in, const int* in_sizes, int n_in,
                              void* d_out, int out_size)
{
    const void*  nums = d_in[0];
    const float* emb  = (const float*)d_in[1];
    const float* Wxh1 = (const float*)d_in[2];
    const float* Whh1 = (const float*)d_in[3];
    const float* b1   = (const float*)d_in[4];
    const float* Wxh2 = (const float*)d_in[5];
    const float* Whh2 = (const float*)d_in[6];
    const float* b2   = (const float*)d_in[7];
    const float* Wl   = (const float*)d_in[8];
    const float* bl   = (const float*)d_in[9];
    const float* Tm   = (const float*)d_in[10];
    float* out = (float*)d_out;

    float *X, *XW;
    cudaGetSymbolAddress((void**)&X,  g_X);
    cudaGetSymbolAddress((void**)&XW, g_XW);

    cudaFuncSetAttribute((const void*)mega, cudaFuncAttributeNonPortableClusterSizeAllowed, 1);

    detect_kernel<<<1, 256>>>((const int*)nums);
    gather_kernel<<<NSEQ, 128>>>(nums, emb);
    expT_kernel<<<VV * VV / 256, 256>>>(Tm);
    zero_flags_kernel<<<NSEQ / 256, 256>>>();

    dim3 gg(512 / 64, NSEQ / 64);
    gemm_bias<<<gg, 256>>>(X, Wxh1, b1, XW);      // XW1 = X@Wxh1 + b1

    cudaLaunchConfig_t cfg = {};
    cfg.gridDim  = dim3(48, 1, 1);
    cfg.blockDim = dim3(512, 1, 1);
    cfg.dynamicSmemBytes = 0;
    cfg.stream = 0;
    cudaLaunchAttribute at[1];
    at[0].id = cudaLaunchAttributeClusterDimension;
    at[0].val.clusterDim.x = CL;
    at[0].val.clusterDim.y = 1;
    at[0].val.clusterDim.z = 1;
    cfg.attrs = at;
    cfg.numAttrs = 1;

    cudaLaunchKernelEx(&cfg, mega, Whh1, (const float*)XW, Whh2, Wxh2, b2, Wl, bl, out);
}

// round 14
// speedup vs baseline: 1.2820x; 1.2820x over previous
#include <cuda_runtime.h>
#include <cstdint>

#define NSEQ 2048
#define DD 512
#define VV 512
#define CL 16

static __device__ float g_X [NSEQ * DD];
static __device__ float g_XW[NSEQ * DD];
static __device__ float g_H2[NSEQ * DD];
static __device__ float g_O [NSEQ * VV];
static __device__ float g_E [VV * VV];
static __device__ int   g_hflag[NSEQ];
static __device__ int   g_oflag[NSEQ];
static __device__ int   g_is64;

__device__ __forceinline__ uint32_t ctarank() {
    uint32_t r; asm("mov.u32 %0, %%cluster_ctarank;" : "=r"(r)); return r;
}
__device__ __forceinline__ uint32_t s2u(const void* p) {
    uint32_t a;
    asm("{ .reg .u64 t; cvta.to.shared.u64 t, %1; cvt.u32.u64 %0, t; }" : "=r"(a) : "l"(p));
    return a;
}
__device__ __forceinline__ uint32_t mapa_(uint32_t laddr, uint32_t r) {
    uint32_t a; asm("mapa.shared::cluster.u32 %0, %1, %2;" : "=r"(a) : "r"(laddr), "r"(r));
    return a;
}
__device__ __forceinline__ void st_async64(uint32_t raddr, uint64_t v, uint32_t rmbar) {
    asm volatile("st.async.shared::cluster.mbarrier::complete_tx::bytes.b64 [%0], %1, [%2];"
                 :: "r"(raddr), "l"(v), "r"(rmbar) : "memory");
}
__device__ __forceinline__ void mbar_init(uint32_t mb, uint32_t cnt) {
    asm volatile("mbarrier.init.shared.b64 [%0], %1;" :: "r"(mb), "r"(cnt) : "memory");
}
__device__ __forceinline__ void mbar_expect(uint32_t mb, uint32_t bytes) {
    asm volatile("mbarrier.arrive.expect_tx.shared.b64 _, [%0], %1;" :: "r"(mb), "r"(bytes) : "memory");
}
__device__ __forceinline__ void mbar_wait(uint32_t mb, uint32_t parity) {
    asm volatile(
        "{\n\t.reg .pred P;\n"
        "W%=:\n\t"
        "mbarrier.try_wait.parity.acquire.cluster.shared::cta.b64 P, [%0], %1, 0x989680;\n\t"
        "@!P bra W%=;\n\t}"
        :: "r"(mb), "r"(parity) : "memory");
}
__device__ __forceinline__ void cl_sync() {
    asm volatile("barrier.cluster.arrive.aligned;" ::: "memory");
    asm volatile("barrier.cluster.wait.aligned;"   ::: "memory");
}
__device__ __forceinline__ int ld_acq(const int* p) {
    int v; asm volatile("ld.acquire.gpu.global.b32 %0, [%1];" : "=r"(v) : "l"(p) : "memory");
    return v;
}
__device__ __forceinline__ void st_rel(int* p, int v) {
    asm volatile("st.release.gpu.global.b32 [%0], %1;" :: "l"(p), "r"(v) : "memory");
}
__device__ __forceinline__ void wait_flag(const int* p) {
    while (ld_acq(p) == 0) { asm volatile("nanosleep.u32 128;"); }
}
__device__ __forceinline__ float wsum(float x) {
#pragma unroll
    for (int o = 16; o; o >>= 1) x += __shfl_xor_sync(0xffffffffu, x, o);
    return x;
}
__device__ __forceinline__ float ex2f_(float x) {
    float y; asm("ex2.approx.f32 %0, %1;" : "=f"(y) : "f"(x)); return y;
}
__device__ __forceinline__ float lg2f_(float x) {
    float y; asm("lg2.approx.f32 %0, %1;" : "=f"(y) : "f"(x)); return y;
}
__device__ __forceinline__ float rcpf_(float x) {
    float y; asm("rcp.approx.f32 %0, %1;" : "=f"(y) : "f"(x)); return y;
}
__device__ __forceinline__ float tanh_ex2(float x) {
    float t = ex2f_(2.8853900817779268f * x);
    float r = rcpf_(t + 1.0f);
    return fmaf(-2.0f, r, 1.0f);
}
__device__ __forceinline__ uint64_t pack2(float a, float b) {
    uint64_t d; asm("mov.b64 %0, {%1, %2};" : "=l"(d) : "f"(a), "f"(b)); return d;
}
__device__ __forceinline__ uint64_t fma2(uint64_t a, uint64_t b, uint64_t c) {
    uint64_t d; asm("fma.rn.f32x2 %0, %1, %2, %3;" : "=l"(d) : "l"(a), "l"(b), "l"(c));
    return d;
}
__device__ __forceinline__ float sum2(uint64_t v) {
    float lo, hi; asm("mov.b64 {%0, %1}, %2;" : "=f"(lo), "=f"(hi) : "l"(v));
    return lo + hi;
}

__global__ void detect_kernel(const int* __restrict__ w) {
    __shared__ int any;
    if (threadIdx.x == 0) any = 0;
    __syncthreads();
    int acc = 0;
    for (int i = threadIdx.x; i < NSEQ / 2; i += blockDim.x) acc |= w[2 * i + 1];
    if (acc) atomicOr(&any, 1);
    __syncthreads();
    if (threadIdx.x == 0) g_is64 = (any == 0) ? 1 : 0;
}
__global__ void gather_kernel(const void* __restrict__ nums, const float* __restrict__ emb) {
    int t = blockIdx.x;
    long long idx = g_is64 ? ((const long long*)nums)[t]
                           : (long long)((const int*)nums)[t];
    const float4* src = (const float4*)(emb + (size_t)idx * DD);
    float4* dst = (float4*)(&g_X[(size_t)t * DD]);
    dst[threadIdx.x] = src[threadIdx.x];
}
__global__ void expT_kernel(const float* __restrict__ T) {
    int i = blockIdx.x * 256 + threadIdx.x;
    g_E[i] = ex2f_(T[i] * 1.4426950408889634f);
}
__global__ void zero_flags_kernel() {
    int i = blockIdx.x * 256 + threadIdx.x;
    g_hflag[i] = 0; g_oflag[i] = 0;
}

__global__ __launch_bounds__(256)
void gemm_bias(const float* __restrict__ A, const float* __restrict__ B,
               const float* __restrict__ bias, float* __restrict__ C)
{
    __shared__ __align__(16) float As[16][68];
    __shared__ __align__(16) float Bs[16][68];
    const int tid = threadIdx.x;
    const int bm = blockIdx.y * 64, bn = blockIdx.x * 64;
    const int tm = tid >> 4, tn = tid & 15;
    float acc[4][4] = {};
    for (int k0 = 0; k0 < 512; k0 += 16) {
        {
            int row = tid >> 2, cg = (tid & 3) * 4;
            float4 v = *(const float4*)(A + (size_t)(bm + row) * 512 + k0 + cg);
            As[cg + 0][row] = v.x; As[cg + 1][row] = v.y;
            As[cg + 2][row] = v.z; As[cg + 3][row] = v.w;
        }
        {
            int row = tid >> 4, col = (tid & 15) * 4;
            *(float4*)&Bs[row][col] = *(const float4*)(B + (size_t)(k0 + row) * 512 + bn + col);
        }
        __syncthreads();
#pragma unroll
        for (int k = 0; k < 16; k++) {
            float4 a = *(const float4*)&As[k][tm * 4];
            float4 b = *(const float4*)&Bs[k][tn * 4];
            float av[4] = {a.x, a.y, a.z, a.w};
            float bv[4] = {b.x, b.y, b.z, b.w};
#pragma unroll
            for (int i = 0; i < 4; i++)
#pragma unroll
                for (int jj = 0; jj < 4; jj++)
                    acc[i][jj] = fmaf(av[i], bv[jj], acc[i][jj]);
        }
        __syncthreads();
    }
    float4 bb = *(const float4*)(bias + bn + tn * 4);
#pragma unroll
    for (int i = 0; i < 4; i++) {
        float4 o;
        o.x = acc[i][0] + bb.x; o.y = acc[i][1] + bb.y;
        o.z = acc[i][2] + bb.z; o.w = acc[i][3] + bb.w;
        *(float4*)(C + (size_t)(bm + tm * 4 + i) * 512 + bn + tn * 4) = o;
    }
}

// ===== mega kernel: 48 CTAs = cluster0 (RNN) + cluster1 (alpha) + 16 builders =====
// Comm: push st.async 8B messages (R11), but tx-updates split across multiple
// mbarrier addresses: role A uses 4 barriers/buffer (h1-lo, h1-hi, h2-lo, h2-hi
// by sender rank half), 128 msgs x 8B = 1024B each. Role B uses 2 barriers/buffer.
__global__ void __launch_bounds__(512, 1)
mega(const float* __restrict__ Whh1, const float* __restrict__ XW1,
     const float* __restrict__ Whh2, const float* __restrict__ Wxh2,
     const float* __restrict__ b2,   const float* __restrict__ Wl,
     const float* __restrict__ bl,   float* __restrict__ out)
{
    __shared__ __align__(16) float sh1[2 * 512];
    __shared__ __align__(16) float sh2[2 * 512];
    __shared__ __align__(8) long long mbar[8];
    const int bid  = blockIdx.x;
    const int tid  = threadIdx.x;
    const int lane = tid & 31;
    const int w    = tid >> 5;
    const float L2E = 1.4426950408889634f;
    const float LN2 = 0.6931471805599453f;

    if (bid < 16) {
        // ---------------- role A: fused 2-layer RNN ----------------
        const uint32_t rank = ctarank();
        const int j0 = (int)rank * 32 + 2 * w;
        uint64_t w1a[8], w1b[8], xa[8], xb[8], ha[8], hb[8];
#pragma unroll
        for (int i = 0; i < 4; i++)
#pragma unroll
            for (int j = 0; j < 2; j++) {
                int k = 128 * i + 4 * lane + 2 * j;
                w1a[2*i+j] = pack2(Whh1[(size_t)k*DD + j0],   Whh1[(size_t)(k+1)*DD + j0]);
                w1b[2*i+j] = pack2(Whh1[(size_t)k*DD + j0+1], Whh1[(size_t)(k+1)*DD + j0+1]);
                xa [2*i+j] = pack2(Wxh2[(size_t)k*DD + j0],   Wxh2[(size_t)(k+1)*DD + j0]);
                xb [2*i+j] = pack2(Wxh2[(size_t)k*DD + j0+1], Wxh2[(size_t)(k+1)*DD + j0+1]);
                ha [2*i+j] = pack2(Whh2[(size_t)k*DD + j0],   Whh2[(size_t)(k+1)*DD + j0]);
                hb [2*i+j] = pack2(Whh2[(size_t)k*DD + j0+1], Whh2[(size_t)(k+1)*DD + j0+1]);
            }
        const float bj0 = b2[j0], bj1 = b2[j0 + 1];
        for (int i = tid; i < 2 * 512; i += 512) { sh1[i] = 0.0f; sh2[i] = 0.0f; }
        const uint32_t b1 = s2u(sh1), b2s = s2u(sh2), mb = s2u(mbar);
        if (tid == 0) {
#pragma unroll
            for (int q = 0; q < 8; q++) mbar_init(mb + 8 * q, 1);
#pragma unroll
            for (int q = 0; q < 8; q++) mbar_expect(mb + 8 * q, 1024);
        }
        __syncthreads();
        cl_sync();
        uint32_t rA1 = 0, rA2 = 0, rM = 0;
        if (lane < CL) {
            rA1 = mapa_(b1  + rank * 128u + 8u * (uint32_t)w, (uint32_t)lane);
            rA2 = mapa_(b2s + rank * 128u + 8u * (uint32_t)w, (uint32_t)lane);
            rM  = mapa_(mb, (uint32_t)lane);
        }
        const uint32_t bh1 = (rank >> 3) * 8u;          // h1 barrier slot offset (0 or 8)
        const uint32_t bh2 = 16u + (rank >> 3) * 8u;    // h2 barrier slot offset (16 or 24)
        float2 xw = *(const float2*)&XW1[j0];

#pragma unroll 1
        for (int r = 0; r <= NSEQ + 1; r++) {
            const uint32_t p = (uint32_t)(r & 1), np = (uint32_t)((r + 1) & 1);
            if (r) {
                const uint32_t ph = (uint32_t)(((r - 1) >> 1) & 1);
                mbar_wait(mb + p * 32u,       ph);
                mbar_wait(mb + p * 32u + 8u,  ph);
                mbar_wait(mb + p * 32u + 16u, ph);
                mbar_wait(mb + p * 32u + 24u, ph);
                if (tid == 0) {
                    mbar_expect(mb + p * 32u,       1024);
                    mbar_expect(mb + p * 32u + 8u,  1024);
                    mbar_expect(mb + p * 32u + 16u, 1024);
                    mbar_expect(mb + p * 32u + 24u, 1024);
                }
            }
            // snapshot publish row early (buffer stable until round r+2 messages)
            const bool ispub = (r >= 2) && ((int)rank == ((r - 2) & 15));
            float pub = 0.0f;
            if (ispub) pub = sh2[p * 512 + tid];

            if (r <= NSEQ) {
                const ulonglong2* c1 = (const ulonglong2*)(sh1 + p * 512);
                ulonglong2 A = c1[lane], B = c1[lane + 32], C = c1[lane + 64], D = c1[lane + 96];
                // h1 chain (critical): matvec + reduce + send ASAP
                if (r < NSEQ) {
                    uint64_t p0=0,p1=0,q0=0,q1=0;
                    p0=fma2(A.x,w1a[0],p0); p1=fma2(A.y,w1a[1],p1);
                    q0=fma2(A.x,w1b[0],q0); q1=fma2(A.y,w1b[1],q1);
                    p0=fma2(B.x,w1a[2],p0); p1=fma2(B.y,w1a[3],p1);
                    q0=fma2(B.x,w1b[2],q0); q1=fma2(B.y,w1b[3],q1);
                    p0=fma2(C.x,w1a[4],p0); p1=fma2(C.y,w1a[5],p1);
                    q0=fma2(C.x,w1b[4],q0); q1=fma2(C.y,w1b[5],q1);
                    p0=fma2(D.x,w1a[6],p0); p1=fma2(D.y,w1a[7],p1);
                    q0=fma2(D.x,w1b[6],q0); q1=fma2(D.y,w1b[7],q1);
                    float ps = wsum(sum2(p0) + sum2(p1));
                    float qs = wsum(sum2(q0) + sum2(q1));
                    float a0 = tanh_ex2(xw.x + ps);
                    float a1 = tanh_ex2(xw.y + qs);
                    if (lane < CL) st_async64(rA1 + np * 2048u, pack2(a0, a1),
                                              rM + np * 32u + bh1);
                } else {
                    if (lane < CL) st_async64(rA1 + np * 2048u, 0ull,
                                              rM + np * 32u + bh1);   // dummy, tx uniform
                }
                // h2 chain: x-matvec + h2-matvec
                uint64_t u0_=0, u1_=0, v0_=0, v1_=0;
                u0_=fma2(A.x,xa[0],u0_); u1_=fma2(A.y,xa[1],u1_);
                v0_=fma2(A.x,xb[0],v0_); v1_=fma2(A.y,xb[1],v1_);
                u0_=fma2(B.x,xa[2],u0_); u1_=fma2(B.y,xa[3],u1_);
                v0_=fma2(B.x,xb[2],v0_); v1_=fma2(B.y,xb[3],v1_);
                u0_=fma2(C.x,xa[4],u0_); u1_=fma2(C.y,xa[5],u1_);
                v0_=fma2(C.x,xb[4],v0_); v1_=fma2(C.y,xb[5],v1_);
                u0_=fma2(D.x,xa[6],u0_); u1_=fma2(D.y,xa[7],u1_);
                v0_=fma2(D.x,xb[6],v0_); v1_=fma2(D.y,xb[7],v1_);
                const ulonglong2* c2 = (const ulonglong2*)(sh2 + p * 512);
                ulonglong2 E = c2[lane], F = c2[lane + 32], G = c2[lane + 64], H = c2[lane + 96];
                u0_=fma2(E.x,ha[0],u0_); u1_=fma2(E.y,ha[1],u1_);
                v0_=fma2(E.x,hb[0],v0_); v1_=fma2(E.y,hb[1],v1_);
                u0_=fma2(F.x,ha[2],u0_); u1_=fma2(F.y,ha[3],u1_);
                v0_=fma2(F.x,hb[2],v0_); v1_=fma2(F.y,hb[3],v1_);
                u0_=fma2(G.x,ha[4],u0_); u1_=fma2(G.y,ha[5],u1_);
                v0_=fma2(G.x,hb[4],v0_); v1_=fma2(G.y,hb[5],v1_);
                u0_=fma2(H.x,ha[6],u0_); u1_=fma2(H.y,ha[7],u1_);
                v0_=fma2(H.x,hb[6],v0_); v1_=fma2(H.y,hb[7],v1_);
                float us = wsum(sum2(u0_) + sum2(u1_));
                float vs = wsum(sum2(v0_) + sum2(v1_));
                float h0 = (r >= 1) ? tanh_ex2(us + bj0) : 0.0f;
                float h1 = (r >= 1) ? tanh_ex2(vs + bj1) : 0.0f;
                if (lane < CL) st_async64(rA2 + np * 2048u, pack2(h0, h1),
                                          rM + np * 32u + bh2);
            }
            // publish row r-2 AFTER sends (absorbed by next wait)
            if (ispub) {
                g_H2[(size_t)(r - 2) * DD + tid] = pub;
                __syncthreads();
                if (tid == 0) st_rel(&g_hflag[r - 2], 1);
            }
            if (r + 1 < NSEQ) xw = *(const float2*)&XW1[(size_t)(r + 1) * DD + j0];
        }
        cl_sync();
    } else if (bid < 32) {
        // ---------------- role B: forward CRF (alpha) ----------------
        const uint32_t rank = ctarank();
        const int u0 = (int)rank * 32 + 2 * w;       // output labels v = u0, u0+1
        uint64_t e0p[8], e1p[8];
#pragma unroll
        for (int i = 0; i < 4; i++)
#pragma unroll
            for (int j = 0; j < 2; j++) {
                int k = 128 * i + 4 * lane + 2 * j;   // source label u
                e0p[2*i+j] = pack2(g_E[(size_t)k*VV + u0],     g_E[(size_t)(k+1)*VV + u0]);
                e1p[2*i+j] = pack2(g_E[(size_t)k*VV + u0 + 1], g_E[(size_t)(k+1)*VV + u0 + 1]);
            }
        for (int i = tid; i < 2 * 512; i += 512) sh1[i] = -1.0e30f;
        const uint32_t b1 = s2u(sh1), mb = s2u(mbar);
        if (tid == 0) {
#pragma unroll
            for (int q = 0; q < 4; q++) mbar_init(mb + 8 * q, 1);
#pragma unroll
            for (int q = 0; q < 4; q++) mbar_expect(mb + 8 * q, 1024);
            wait_flag(&g_oflag[0]);
            sh1[0] = g_O[0] * L2E;                    // a0[BOS] = O[0][BOS]
        }
        __syncthreads();
        cl_sync();
        uint32_t rA = 0, rM = 0;
        if (lane < CL) {
            rA = mapa_(b1 + rank * 128u + 8u * (uint32_t)w, (uint32_t)lane);
            rM = mapa_(mb, (uint32_t)lane);
        }
        const uint32_t bsl = (rank >> 3) * 8u;
        wait_flag(&g_oflag[1]);
        float2 ov = *(const float2*)&g_O[(size_t)VV + u0];
        float o0 = ov.x * L2E, o1 = ov.y * L2E;

#pragma unroll 1
        for (int si = 0; si < NSEQ - 1; si++) {
            const uint32_t p = (uint32_t)(si & 1);
            if (si) {
                const uint32_t ph = (uint32_t)(((si - 1) >> 1) & 1);
                mbar_wait(mb + p * 16u,      ph);
                mbar_wait(mb + p * 16u + 8u, ph);
                if (tid == 0) {
                    mbar_expect(mb + p * 16u,      1024);
                    mbar_expect(mb + p * 16u + 8u, 1024);
                }
            }
            const float* cbuf = sh1 + p * 512;
            const float offc = cbuf[0];               // a[BOS] as offset
            sh2[p * 512 + tid] = ex2f_(cbuf[tid] - offc);
            __syncthreads();
            const ulonglong2* ep = (const ulonglong2*)(sh2 + p * 512);
            ulonglong2 A = ep[lane], B = ep[lane + 32], C = ep[lane + 64], D = ep[lane + 96];
            uint64_t p0=0,p1=0,q0=0,q1=0;
            p0=fma2(A.x,e0p[0],p0); p1=fma2(A.y,e0p[1],p1);
            q0=fma2(A.x,e1p[0],q0); q1=fma2(A.y,e1p[1],q1);
            p0=fma2(B.x,e0p[2],p0); p1=fma2(B.y,e0p[3],p1);
            q0=fma2(B.x,e1p[2],q0); q1=fma2(B.y,e1p[3],q1);
            p0=fma2(C.x,e0p[4],p0); p1=fma2(C.y,e0p[5],p1);
            q0=fma2(C.x,e1p[4],q0); q1=fma2(C.y,e1p[5],q1);
            p0=fma2(D.x,e0p[6],p0); p1=fma2(D.y,e0p[7],p1);
            q0=fma2(D.x,e1p[6],q0); q1=fma2(D.y,e1p[7],q1);
            float s0 = wsum(sum2(p0) + sum2(p1));
            float s1 = wsum(sum2(q0) + sum2(q1));
            float al0 = o0 + offc + lg2f_(s0);
            float al1 = o1 + offc + lg2f_(s1);
            if (si == NSEQ - 2) {
                if (rank == 0 && tid == 0) out[0] = al1 * LN2;   // a_{n-1}[EOS]
            } else {
                const uint32_t np = (uint32_t)((si + 1) & 1);
                if (lane < CL) st_async64(rA + np * 2048u, pack2(al0, al1),
                                          rM + np * 16u + bsl);
                int row = si + 2;
                wait_flag(&g_oflag[row]);
                float2 onx = *(const float2*)&g_O[(size_t)row * VV + u0];
                o0 = onx.x * L2E; o1 = onx.y * L2E;
            }
        }
        cl_sync();
    } else {
        // ---------------- role C: O-row builders ----------------
        const int b = bid - 32;       // 0..15
        for (int row = b; row < NSEQ; row += 16) {
            wait_flag(&g_hflag[row]);
            sh1[tid] = g_H2[(size_t)row * DD + tid];
            __syncthreads();
            float acc = bl[tid];
            const float* wc = Wl + tid;
#pragma unroll 16
            for (int k = 0; k < DD; k++) acc = fmaf(sh1[k], wc[(size_t)k * VV], acc);
            g_O[(size_t)row * VV + tid] = acc;
            __syncthreads();
            if (tid == 0) st_rel(&g_oflag[row], 1);
        }
    }
}

extern "C" void kernel_launch(void* const* d_in, const int* in_sizes, int n_in,
                              void* d_out, int out_size)
{
    const void*  nums = d_in[0];
    const float* emb  = (const float*)d_in[1];
    const float* Wxh1 = (const float*)d_in[2];
    const float* Whh1 = (const float*)d_in[3];
    const float* b1   = (const float*)d_in[4];
    const float* Wxh2 = (const float*)d_in[5];
    const float* Whh2 = (const float*)d_in[6];
    const float* b2   = (const float*)d_in[7];
    const float* Wl   = (const float*)d_in[8];
    const float* bl   = (const float*)d_in[9];
    const float* Tm   = (const float*)d_in[10];
    float* out = (float*)d_out;

    float *X, *XW;
    cudaGetSymbolAddress((void**)&X,  g_X);
    cudaGetSymbolAddress((void**)&XW, g_XW);

    cudaFuncSetAttribute((const void*)mega, cudaFuncAttributeNonPortableClusterSizeAllowed, 1);

    detect_kernel<<<1, 256>>>((const int*)nums);
    gather_kernel<<<NSEQ, 128>>>(nums, emb);
    expT_kernel<<<VV * VV / 256, 256>>>(Tm);
    zero_flags_kernel<<<NSEQ / 256, 256>>>();

    dim3 gg(512 / 64, NSEQ / 64);
    gemm_bias<<<gg, 256>>>(X, Wxh1, b1, XW);      // XW1 = X@Wxh1 + b1

    cudaLaunchConfig_t cfg = {};
    cfg.gridDim  = dim3(48, 1, 1);
    cfg.blockDim = dim3(512, 1, 1);
    cfg.dynamicSmemBytes = 0;
    cfg.stream = 0;
    cudaLaunchAttribute at[1];
    at[0].id = cudaLaunchAttributeClusterDimension;
    at[0].val.clusterDim.x = CL;
    at[0].val.clusterDim.y = 1;
    at[0].val.clusterDim.z = 1;
    cfg.attrs = at;
    cfg.numAttrs = 1;

    cudaLaunchKernelEx(&cfg, mega, Whh1, (const float*)XW, Whh2, Wxh2, b2, Wl, bl, out);
}

// round 16
// speedup vs baseline: 1.6230x; 1.2660x over previous
#include <cuda_runtime.h>
#include <cstdint>

#define NSEQ 2048
#define DD 512
#define VV 512
#define CL 16

static __device__ float g_X [NSEQ * DD];
static __device__ float g_XW[NSEQ * DD];
static __device__ float g_H2[NSEQ * DD];
static __device__ float g_O [NSEQ * VV];
static __device__ float g_E [VV * VV];
static __device__ int   g_hflag[NSEQ];
static __device__ int   g_oflag[NSEQ];
static __device__ int   g_is64;

__device__ __forceinline__ uint32_t ctarank() {
    uint32_t r; asm("mov.u32 %0, %%cluster_ctarank;" : "=r"(r)); return r;
}
__device__ __forceinline__ uint32_t s2u(const void* p) {
    uint32_t a;
    asm("{ .reg .u64 t; cvta.to.shared.u64 t, %1; cvt.u32.u64 %0, t; }" : "=r"(a) : "l"(p));
    return a;
}
__device__ __forceinline__ uint32_t mapa_(uint32_t laddr, uint32_t r) {
    uint32_t a; asm("mapa.shared::cluster.u32 %0, %1, %2;" : "=r"(a) : "r"(laddr), "r"(r));
    return a;
}
__device__ __forceinline__ void st_async64(uint32_t raddr, uint64_t v, uint32_t rmbar) {
    asm volatile("st.async.shared::cluster.mbarrier::complete_tx::bytes.b64 [%0], %1, [%2];"
                 :: "r"(raddr), "l"(v), "r"(rmbar) : "memory");
}
__device__ __forceinline__ void st_async128(uint32_t raddr, float4 v, uint32_t rmbar) {
    asm volatile("st.async.shared::cluster.mbarrier::complete_tx::bytes.v4.b32 [%0], {%1, %2, %3, %4}, [%5];"
                 :: "r"(raddr), "f"(v.x), "f"(v.y), "f"(v.z), "f"(v.w), "r"(rmbar) : "memory");
}
__device__ __forceinline__ void mbar_init(uint32_t mb, uint32_t cnt) {
    asm volatile("mbarrier.init.shared.b64 [%0], %1;" :: "r"(mb), "r"(cnt) : "memory");
}
__device__ __forceinline__ void mbar_expect(uint32_t mb, uint32_t bytes) {
    asm volatile("mbarrier.arrive.expect_tx.shared.b64 _, [%0], %1;" :: "r"(mb), "r"(bytes) : "memory");
}
__device__ __forceinline__ void mbar_wait(uint32_t mb, uint32_t parity) {
    asm volatile(
        "{\n\t.reg .pred P;\n"
        "W%=:\n\t"
        "mbarrier.try_wait.parity.acquire.cluster.shared::cta.b64 P, [%0], %1, 0x989680;\n\t"
        "@!P bra W%=;\n\t}"
        :: "r"(mb), "r"(parity) : "memory");
}
__device__ __forceinline__ void cl_sync() {
    asm volatile("barrier.cluster.arrive.aligned;" ::: "memory");
    asm volatile("barrier.cluster.wait.aligned;"   ::: "memory");
}
__device__ __forceinline__ int ld_acq(const int* p) {
    int v; asm volatile("ld.acquire.gpu.global.b32 %0, [%1];" : "=r"(v) : "l"(p) : "memory");
    return v;
}
__device__ __forceinline__ void st_rel(int* p, int v) {
    asm volatile("st.release.gpu.global.b32 [%0], %1;" :: "l"(p), "r"(v) : "memory");
}
__device__ __forceinline__ void wait_flag(const int* p) {
    while (ld_acq(p) == 0) { asm volatile("nanosleep.u32 128;"); }
}
__device__ __forceinline__ float ex2f_(float x) {
    float y; asm("ex2.approx.f32 %0, %1;" : "=f"(y) : "f"(x)); return y;
}
__device__ __forceinline__ float lg2f_(float x) {
    float y; asm("lg2.approx.f32 %0, %1;" : "=f"(y) : "f"(x)); return y;
}
__device__ __forceinline__ float rcpf_(float x) {
    float y; asm("rcp.approx.f32 %0, %1;" : "=f"(y) : "f"(x)); return y;
}
__device__ __forceinline__ float tanh_ex2(float x) {
    float t = ex2f_(2.8853900817779268f * x);
    float r = rcpf_(t + 1.0f);
    return fmaf(-2.0f, r, 1.0f);
}
__device__ __forceinline__ float wsum(float x) {
#pragma unroll
    for (int o = 16; o; o >>= 1) x += __shfl_xor_sync(0xffffffffu, x, o);
    return x;
}
__device__ __forceinline__ uint64_t pack2(float a, float b) {
    uint64_t d; asm("mov.b64 %0, {%1, %2};" : "=l"(d) : "f"(a), "f"(b)); return d;
}
__device__ __forceinline__ uint64_t fma2(uint64_t a, uint64_t b, uint64_t c) {
    uint64_t d; asm("fma.rn.f32x2 %0, %1, %2, %3;" : "=l"(d) : "l"(a), "l"(b), "l"(c));
    return d;
}
__device__ __forceinline__ float sum2(uint64_t v) {
    float lo, hi; asm("mov.b64 {%0, %1}, %2;" : "=f"(lo), "=f"(hi) : "l"(v));
    return lo + hi;
}

__global__ void detect_kernel(const int* __restrict__ w) {
    __shared__ int any;
    if (threadIdx.x == 0) any = 0;
    __syncthreads();
    int acc = 0;
    for (int i = threadIdx.x; i < NSEQ / 2; i += blockDim.x) acc |= w[2 * i + 1];
    if (acc) atomicOr(&any, 1);
    __syncthreads();
    if (threadIdx.x == 0) g_is64 = (any == 0) ? 1 : 0;
}
__global__ void gather_kernel(const void* __restrict__ nums, const float* __restrict__ emb) {
    int t = blockIdx.x;
    long long idx = g_is64 ? ((const long long*)nums)[t]
                           : (long long)((const int*)nums)[t];
    const float4* src = (const float4*)(emb + (size_t)idx * DD);
    float4* dst = (float4*)(&g_X[(size_t)t * DD]);
    dst[threadIdx.x] = src[threadIdx.x];
}
__global__ void expT_kernel(const float* __restrict__ T) {
    int i = blockIdx.x * 256 + threadIdx.x;
    g_E[i] = ex2f_(T[i] * 1.4426950408889634f);
}
__global__ void zero_flags_kernel() {
    int i = blockIdx.x * 256 + threadIdx.x;
    g_hflag[i] = 0; g_oflag[i] = 0;
}

__global__ __launch_bounds__(256)
void gemm_bias(const float* __restrict__ A, const float* __restrict__ B,
               const float* __restrict__ bias, float* __restrict__ C)
{
    __shared__ __align__(16) float As[16][68];
    __shared__ __align__(16) float Bs[16][68];
    const int tid = threadIdx.x;
    const int bm = blockIdx.y * 64, bn = blockIdx.x * 64;
    const int tm = tid >> 4, tn = tid & 15;
    float acc[4][4] = {};
    for (int k0 = 0; k0 < 512; k0 += 16) {
        {
            int row = tid >> 2, cg = (tid & 3) * 4;
            float4 v = *(const float4*)(A + (size_t)(bm + row) * 512 + k0 + cg);
            As[cg + 0][row] = v.x; As[cg + 1][row] = v.y;
            As[cg + 2][row] = v.z; As[cg + 3][row] = v.w;
        }
        {
            int row = tid >> 4, col = (tid & 15) * 4;
            *(float4*)&Bs[row][col] = *(const float4*)(B + (size_t)(k0 + row) * 512 + bn + col);
        }
        __syncthreads();
#pragma unroll
        for (int k = 0; k < 16; k++) {
            float4 a = *(const float4*)&As[k][tm * 4];
            float4 b = *(const float4*)&Bs[k][tn * 4];
            float av[4] = {a.x, a.y, a.z, a.w};
            float bv[4] = {b.x, b.y, b.z, b.w};
#pragma unroll
            for (int i = 0; i < 4; i++)
#pragma unroll
                for (int jj = 0; jj < 4; jj++)
                    acc[i][jj] = fmaf(av[i], bv[jj], acc[i][jj]);
        }
        __syncthreads();
    }
    float4 bb = *(const float4*)(bias + bn + tn * 4);
#pragma unroll
    for (int i = 0; i < 4; i++) {
        float4 o;
        o.x = acc[i][0] + bb.x; o.y = acc[i][1] + bb.y;
        o.z = acc[i][2] + bb.z; o.w = acc[i][3] + bb.w;
        *(float4*)(C + (size_t)(bm + tm * 4 + i) * 512 + bn + tn * 4) = o;
    }
}

// ===== mega: 48 CTAs = cluster0 RNN (combined 16B msgs) + cluster1 alpha + 16 builders =====
// RNN state buffer: 1024 floats = 256 chunks of {h1_j0, h1_j1, h2_j0, h2_j1},
// chunk c (sender rank=c>>4, warp=c&15) covers j0 = (c>>4)*32 + 2*(c&15).
// One 16B st.async.v4 per warp per peer = 256 msgs/round, expect_tx 4096 B.
__global__ void __launch_bounds__(512, 1)
mega(const float* __restrict__ Whh1, const float* __restrict__ XW1,
     const float* __restrict__ Whh2, const float* __restrict__ Wxh2,
     const float* __restrict__ b2,   const float* __restrict__ Wl,
     const float* __restrict__ bl,   float* __restrict__ out)
{
    __shared__ __align__(16) float shc[2 * 1024];
    __shared__ __align__(8) long long mbar[2];
    const int bid  = blockIdx.x;
    const int tid  = threadIdx.x;
    const int lane = tid & 31;
    const int w    = tid >> 5;
    const float L2E = 1.4426950408889634f;
    const float LN2 = 0.6931471805599453f;

    if (bid < 16) {
        // -------- role A: fused 2-layer RNN, combined-message push --------
        const uint32_t rank = ctarank();
        const int j0 = (int)rank * 32 + 2 * w;
        uint64_t w1a[8], w1b[8], xa[8], xb[8], ha[8], hb[8];
#pragma unroll
        for (int i = 0; i < 8; i++) {
            int c  = lane + 32 * i;
            int kb = ((c >> 4) << 5) + ((c & 15) << 1);   // k of chunk c
            w1a[i] = pack2(Whh1[(size_t)kb*DD + j0],   Whh1[(size_t)(kb+1)*DD + j0]);
            w1b[i] = pack2(Whh1[(size_t)kb*DD + j0+1], Whh1[(size_t)(kb+1)*DD + j0+1]);
            xa [i] = pack2(Wxh2[(size_t)kb*DD + j0],   Wxh2[(size_t)(kb+1)*DD + j0]);
            xb [i] = pack2(Wxh2[(size_t)kb*DD + j0+1], Wxh2[(size_t)(kb+1)*DD + j0+1]);
            ha [i] = pack2(Whh2[(size_t)kb*DD + j0],   Whh2[(size_t)(kb+1)*DD + j0]);
            hb [i] = pack2(Whh2[(size_t)kb*DD + j0+1], Whh2[(size_t)(kb+1)*DD + j0+1]);
        }
        const float bj0 = b2[j0], bj1 = b2[j0 + 1];
        for (int i = tid; i < 2 * 1024; i += 512) shc[i] = 0.0f;   // h1 = h2 = 0
        const uint32_t bs = s2u(shc), mb = s2u(mbar);
        if (tid == 0) {
            mbar_init(mb, 1);      mbar_init(mb + 8, 1);
            mbar_expect(mb, 4096); mbar_expect(mb + 8, 4096);
        }
        __syncthreads();
        cl_sync();
        uint32_t rA = 0, rM = 0;
        if (lane < CL) {
            rA = mapa_(bs + (rank * 16u + (uint32_t)w) * 16u, (uint32_t)lane);
            rM = mapa_(mb, (uint32_t)lane);
        }
        float2 xw = *(const float2*)&XW1[j0];

#pragma unroll 1
        for (int r = 0; r <= NSEQ + 1; r++) {
            const uint32_t p = (uint32_t)(r & 1), np = (uint32_t)((r + 1) & 1);
            if (r) {
                mbar_wait(mb + 8 * p, (uint32_t)(((r - 1) >> 1) & 1));
                if (tid == 0) mbar_expect(mb + 8 * p, 4096);
            }
            // snapshot publish row early (buffer stable until our sends complete)
            const bool ispub = (r >= 2) && ((int)rank == ((r - 2) & 15));
            float pub = 0.0f;
            if (ispub) {
                int c = ((tid >> 5) << 4) + ((tid >> 1) & 15);
                pub = shc[p * 1024 + c * 4 + 2 + (tid & 1)];
            }
            if (r <= NSEQ) {
                const ulonglong2* cb = (const ulonglong2*)(shc + p * 1024);
                uint64_t p0=0,p1=0,q0=0,q1=0,u0=0,u1=0,v0=0,v1=0;
#pragma unroll
                for (int i = 0; i < 8; i += 2) {
                    ulonglong2 A = cb[lane + 32 * i];
                    ulonglong2 B = cb[lane + 32 * (i + 1)];
                    p0 = fma2(A.x, w1a[i], p0);     q0 = fma2(A.x, w1b[i], q0);
                    u0 = fma2(A.x, xa[i],  u0);     v0 = fma2(A.x, xb[i],  v0);
                    u1 = fma2(A.y, ha[i],  u1);     v1 = fma2(A.y, hb[i],  v1);
                    p1 = fma2(B.x, w1a[i+1], p1);   q1 = fma2(B.x, w1b[i+1], q1);
                    u0 = fma2(B.x, xa[i+1],  u0);   v0 = fma2(B.x, xb[i+1],  v0);
                    u1 = fma2(B.y, ha[i+1],  u1);   v1 = fma2(B.y, hb[i+1],  v1);
                }
                float ps = sum2(p0) + sum2(p1);
                float qs = sum2(q0) + sum2(q1);
                float us = sum2(u0) + sum2(u1);
                float vs = sum2(v0) + sum2(v1);
#pragma unroll
                for (int o = 16; o; o >>= 1) {
                    ps += __shfl_xor_sync(0xffffffffu, ps, o);
                    qs += __shfl_xor_sync(0xffffffffu, qs, o);
                    us += __shfl_xor_sync(0xffffffffu, us, o);
                    vs += __shfl_xor_sync(0xffffffffu, vs, o);
                }
                float a0 = (r < NSEQ) ? tanh_ex2(xw.x + ps) : 0.0f;
                float a1 = (r < NSEQ) ? tanh_ex2(xw.y + qs) : 0.0f;
                float h0 = (r >= 1) ? tanh_ex2(us + bj0) : 0.0f;   // h2_{r-1}
                float h1v = (r >= 1) ? tanh_ex2(vs + bj1) : 0.0f;
                if (lane < CL)
                    st_async128(rA + np * 4096u, make_float4(a0, a1, h0, h1v), rM + 8u * np);
            }
            if (ispub) {
                g_H2[(size_t)(r - 2) * DD + tid] = pub;
                __syncthreads();
                if (tid == 0) st_rel(&g_hflag[r - 2], 1);
            }
            if (r + 1 < NSEQ) xw = *(const float2*)&XW1[(size_t)(r + 1) * DD + j0];
        }
        cl_sync();
    } else if (bid < 32) {
        // -------- role B: forward CRF (alpha), R11 push --------
        const uint32_t rank = ctarank();
        const int u0 = (int)rank * 32 + 2 * w;
        float* abuf = shc;            // alpha state, 2 x 512
        float* ebuf = shc + 1024;     // exp scratch, 2 x 512
        uint64_t e0p[8], e1p[8];
#pragma unroll
        for (int i = 0; i < 4; i++)
#pragma unroll
            for (int j = 0; j < 2; j++) {
                int k = 128 * i + 4 * lane + 2 * j;
                e0p[2*i+j] = pack2(g_E[(size_t)k*VV + u0],     g_E[(size_t)(k+1)*VV + u0]);
                e1p[2*i+j] = pack2(g_E[(size_t)k*VV + u0 + 1], g_E[(size_t)(k+1)*VV + u0 + 1]);
            }
        for (int i = tid; i < 2 * 512; i += 512) abuf[i] = -1.0e30f;
        const uint32_t b1 = s2u(abuf), mb = s2u(mbar);
        if (tid == 0) {
            mbar_init(mb, 1);      mbar_init(mb + 8, 1);
            mbar_expect(mb, 2048); mbar_expect(mb + 8, 2048);
            wait_flag(&g_oflag[0]);
            abuf[0] = g_O[0] * L2E;                   // a0[BOS]
        }
        __syncthreads();
        cl_sync();
        uint32_t rA = 0, rM = 0;
        if (lane < CL) {
            rA = mapa_(b1 + rank * 128u + 8u * (uint32_t)w, (uint32_t)lane);
            rM = mapa_(mb, (uint32_t)lane);
        }
        wait_flag(&g_oflag[1]);
        float2 ov = *(const float2*)&g_O[(size_t)VV + u0];
        float o0 = ov.x * L2E, o1 = ov.y * L2E;

#pragma unroll 1
        for (int si = 0; si < NSEQ - 1; si++) {
            const uint32_t p = (uint32_t)(si & 1);
            if (si) {
                mbar_wait(mb + 8 * p, (uint32_t)(((si - 1) >> 1) & 1));
                if (tid == 0) mbar_expect(mb + 8 * p, 2048);
            }
            const float* cbuf = abuf + p * 512;
            const float offc = cbuf[0];
            ebuf[p * 512 + tid] = ex2f_(cbuf[tid] - offc);
            __syncthreads();
            const ulonglong2* ep = (const ulonglong2*)(ebuf + p * 512);
            ulonglong2 A = ep[lane], B = ep[lane + 32], C = ep[lane + 64], D = ep[lane + 96];
            uint64_t p0=0,p1=0,q0=0,q1=0;
            p0=fma2(A.x,e0p[0],p0); p1=fma2(A.y,e0p[1],p1);
            q0=fma2(A.x,e1p[0],q0); q1=fma2(A.y,e1p[1],q1);
            p0=fma2(B.x,e0p[2],p0); p1=fma2(B.y,e0p[3],p1);
            q0=fma2(B.x,e1p[2],q0); q1=fma2(B.y,e1p[3],q1);
            p0=fma2(C.x,e0p[4],p0); p1=fma2(C.y,e0p[5],p1);
            q0=fma2(C.x,e1p[4],q0); q1=fma2(C.y,e1p[5],q1);
            p0=fma2(D.x,e0p[6],p0); p1=fma2(D.y,e0p[7],p1);
            q0=fma2(D.x,e1p[6],q0); q1=fma2(D.y,e1p[7],q1);
            float s0 = wsum(sum2(p0) + sum2(p1));
            float s1 = wsum(sum2(q0) + sum2(q1));
            float al0 = o0 + offc + lg2f_(s0);
            float al1 = o1 + offc + lg2f_(s1);
            if (si == NSEQ - 2) {
                if (rank == 0 && tid == 0) out[0] = al1 * LN2;   // a_{n-1}[EOS]
            } else {
                const uint32_t np = (uint32_t)((si + 1) & 1);
                if (lane < CL) st_async64(rA + np * 2048u, pack2(al0, al1), rM + 8u * np);
                int row = si + 2;
                wait_flag(&g_oflag[row]);
                float2 onx = *(const float2*)&g_O[(size_t)row * VV + u0];
                o0 = onx.x * L2E; o1 = onx.y * L2E;
            }
        }
        cl_sync();
    } else {
        // -------- role C: O-row builders --------
        const int b = bid - 32;
        for (int row = b; row < NSEQ; row += 16) {
            wait_flag(&g_hflag[row]);
            shc[tid] = g_H2[(size_t)row * DD + tid];
            __syncthreads();
            float acc = bl[tid];
            const float* wc = Wl + tid;
#pragma unroll 16
            for (int k = 0; k < DD; k++) acc = fmaf(shc[k], wc[(size_t)k * VV], acc);
            g_O[(size_t)row * VV + tid] = acc;
            __syncthreads();
            if (tid == 0) st_rel(&g_oflag[row], 1);
        }
    }
}

extern "C" void kernel_launch(void* const* d_in, const int* in_sizes, int n_in,
                              void* d_out, int out_size)
{
    const void*  nums = d_in[0];
    const float* emb  = (const float*)d_in[1];
    const float* Wxh1 = (const float*)d_in[2];
    const float* Whh1 = (const float*)d_in[3];
    const float* b1   = (const float*)d_in[4];
    const float* Wxh2 = (const float*)d_in[5];
    const float* Whh2 = (const float*)d_in[6];
    const float* b2   = (const float*)d_in[7];
    const float* Wl   = (const float*)d_in[8];
    const float* bl   = (const float*)d_in[9];
    const float* Tm   = (const float*)d_in[10];
    float* out = (float*)d_out;

    float *X, *XW;
    cudaGetSymbolAddress((void**)&X,  g_X);
    cudaGetSymbolAddress((void**)&XW, g_XW);

    cudaFuncSetAttribute((const void*)mega, cudaFuncAttributeNonPortableClusterSizeAllowed, 1);

    detect_kernel<<<1, 256>>>((const int*)nums);
    gather_kernel<<<NSEQ, 128>>>(nums, emb);
    expT_kernel<<<VV * VV / 256, 256>>>(Tm);
    zero_flags_kernel<<<NSEQ / 256, 256>>>();

    dim3 gg(512 / 64, NSEQ / 64);
    gemm_bias<<<gg, 256>>>(X, Wxh1, b1, XW);      // XW1 = X@Wxh1 + b1

    cudaLaunchConfig_t cfg = {};
    cfg.gridDim  = dim3(48, 1, 1);
    cfg.blockDim = dim3(512, 1, 1);
    cfg.dynamicSmemBytes = 0;
    cfg.stream = 0;
    cudaLaunchAttribute at[1];
    at[0].id = cudaLaunchAttributeClusterDimension;
    at[0].val.clusterDim.x = CL;
    at[0].val.clusterDim.y = 1;
    at[0].val.clusterDim.z = 1;
    cfg.attrs = at;
    cfg.numAttrs = 1;

    cudaLaunchKernelEx(&cfg, mega, Whh1, (const float*)XW, Whh2, Wxh2, b2, Wl, bl, out);
}